// round 7
// baseline (speedup 1.0000x reference)
#include <cuda_runtime.h>
#include <math.h>

// Problem constants
#define B_   2
#define HH   56
#define WW   56
#define C_   256
#define NH   8
#define HD   32
#define TOK  (B_*HH*WW)      // 6272
#define POS  (HH*WW)         // 3136
#define QSCALE 0.17677669529663687f   // 32^-0.5

__device__ float g_q[B_*NH*POS*HD];
__device__ float g_k[B_*NH*POS*HD];
__device__ float g_v[B_*NH*POS*HD];
__device__ float g_att[TOK*C_];

__device__ __forceinline__ unsigned f2tf32(float f) {
    unsigned u;
    asm("cvt.rna.tf32.f32 %0, %1;" : "=r"(u) : "f"(f));
    return u;
}

// ---------------------------------------------------------------------------
// tf32 tensor-core GEMM, double-buffered (unchanged from R6).
// ---------------------------------------------------------------------------
#define ASTR 20
#define BSTR 136
#define NKT  16

__global__ __launch_bounds__(256) void gemm_tf32_kernel(
    const float* __restrict__ A, const float* __restrict__ Bw,
    const float* __restrict__ bias, float* __restrict__ Cout,
    int N, int mode)
{
    __shared__ alignas(16) unsigned As[2][128*ASTR];
    __shared__ alignas(16) unsigned Bs[2][16*BSTR];

    const float* __restrict__ Ap = A ? A : g_att;

    const int tid  = threadIdx.x;
    const int lane = tid & 31;
    const int w    = tid >> 5;
    const int wm   = w >> 1;
    const int wn   = w & 1;
    const int g    = lane >> 2;
    const int tg   = lane & 3;

    const int row0 = blockIdx.y * 128;
    const int col0 = blockIdx.x * 128;

    const int a_r0 = tid >> 2,          a_c0 = (tid & 3) << 2;
    const int a_r1 = (tid + 256) >> 2,  a_c1 = a_c0;
    const int b_r0 = tid >> 5,          b_c0 = (tid & 31) << 2;
    const int b_r1 = (tid + 256) >> 5,  b_c1 = b_c0;

    float c[2][8][4];
    #pragma unroll
    for (int mt = 0; mt < 2; mt++)
        #pragma unroll
        for (int nt = 0; nt < 8; nt++)
            #pragma unroll
            for (int i = 0; i < 4; i++)
                c[mt][nt][i] = 0.0f;

    float4 sa0, sa1, sb0, sb1;

    sa0 = *(const float4*)&Ap[(long)(row0 + a_r0)*256 + a_c0];
    sa1 = *(const float4*)&Ap[(long)(row0 + a_r1)*256 + a_c1];
    sb0 = *(const float4*)&Bw[(long)b_r0*N + col0 + b_c0];
    sb1 = *(const float4*)&Bw[(long)b_r1*N + col0 + b_c1];
    {
        uint4 u;
        u.x=f2tf32(sa0.x); u.y=f2tf32(sa0.y); u.z=f2tf32(sa0.z); u.w=f2tf32(sa0.w);
        *(uint4*)&As[0][a_r0*ASTR + a_c0] = u;
        u.x=f2tf32(sa1.x); u.y=f2tf32(sa1.y); u.z=f2tf32(sa1.z); u.w=f2tf32(sa1.w);
        *(uint4*)&As[0][a_r1*ASTR + a_c1] = u;
        u.x=f2tf32(sb0.x); u.y=f2tf32(sb0.y); u.z=f2tf32(sb0.z); u.w=f2tf32(sb0.w);
        *(uint4*)&Bs[0][b_r0*BSTR + b_c0] = u;
        u.x=f2tf32(sb1.x); u.y=f2tf32(sb1.y); u.z=f2tf32(sb1.z); u.w=f2tf32(sb1.w);
        *(uint4*)&Bs[0][b_r1*BSTR + b_c1] = u;
    }
    __syncthreads();

    #pragma unroll
    for (int kt = 0; kt < NKT; kt++) {
        const int cur = kt & 1;
        const int nxt = cur ^ 1;

        if (kt < NKT-1) {
            int k0 = (kt+1) * 16;
            sa0 = *(const float4*)&Ap[(long)(row0 + a_r0)*256 + k0 + a_c0];
            sa1 = *(const float4*)&Ap[(long)(row0 + a_r1)*256 + k0 + a_c1];
            sb0 = *(const float4*)&Bw[(long)(k0 + b_r0)*N + col0 + b_c0];
            sb1 = *(const float4*)&Bw[(long)(k0 + b_r1)*N + col0 + b_c1];
        }

        #pragma unroll
        for (int kc = 0; kc < 16; kc += 8) {
            unsigned a[2][4], bf[8][2];
            #pragma unroll
            for (int mt = 0; mt < 2; mt++) {
                int rb = wm*32 + mt*16;
                a[mt][0] = As[cur][(rb + g    )*ASTR + kc + tg    ];
                a[mt][1] = As[cur][(rb + g + 8)*ASTR + kc + tg    ];
                a[mt][2] = As[cur][(rb + g    )*ASTR + kc + tg + 4];
                a[mt][3] = As[cur][(rb + g + 8)*ASTR + kc + tg + 4];
            }
            #pragma unroll
            for (int nt = 0; nt < 8; nt++) {
                int cb = wn*64 + nt*8;
                bf[nt][0] = Bs[cur][(kc + tg    )*BSTR + cb + g];
                bf[nt][1] = Bs[cur][(kc + tg + 4)*BSTR + cb + g];
            }
            #pragma unroll
            for (int mt = 0; mt < 2; mt++)
                #pragma unroll
                for (int nt = 0; nt < 8; nt++)
                    asm volatile(
                        "mma.sync.aligned.m16n8k8.row.col.f32.tf32.tf32.f32 "
                        "{%0,%1,%2,%3}, {%4,%5,%6,%7}, {%8,%9}, {%0,%1,%2,%3};"
                        : "+f"(c[mt][nt][0]), "+f"(c[mt][nt][1]),
                          "+f"(c[mt][nt][2]), "+f"(c[mt][nt][3])
                        : "r"(a[mt][0]), "r"(a[mt][1]), "r"(a[mt][2]), "r"(a[mt][3]),
                          "r"(bf[nt][0]), "r"(bf[nt][1]));
        }

        if (kt < NKT-1) {
            uint4 u;
            u.x=f2tf32(sa0.x); u.y=f2tf32(sa0.y); u.z=f2tf32(sa0.z); u.w=f2tf32(sa0.w);
            *(uint4*)&As[nxt][a_r0*ASTR + a_c0] = u;
            u.x=f2tf32(sa1.x); u.y=f2tf32(sa1.y); u.z=f2tf32(sa1.z); u.w=f2tf32(sa1.w);
            *(uint4*)&As[nxt][a_r1*ASTR + a_c1] = u;
            u.x=f2tf32(sb0.x); u.y=f2tf32(sb0.y); u.z=f2tf32(sb0.z); u.w=f2tf32(sb0.w);
            *(uint4*)&Bs[nxt][b_r0*BSTR + b_c0] = u;
            u.x=f2tf32(sb1.x); u.y=f2tf32(sb1.y); u.z=f2tf32(sb1.z); u.w=f2tf32(sb1.w);
            *(uint4*)&Bs[nxt][b_r1*BSTR + b_c1] = u;
        }
        __syncthreads();
    }

    #pragma unroll
    for (int mt = 0; mt < 2; mt++) {
        int r_lo = row0 + wm*32 + mt*16 + g;
        int r_hi = r_lo + 8;
        #pragma unroll
        for (int nt = 0; nt < 8; nt++) {
            int gj = col0 + wn*64 + nt*8 + 2*tg;
            float b0 = bias[gj], b1 = bias[gj+1];
            if (mode == 1) {
                Cout[(long)r_lo*N + gj    ] = c[mt][nt][0] + b0;
                Cout[(long)r_lo*N + gj + 1] = c[mt][nt][1] + b1;
                Cout[(long)r_hi*N + gj    ] = c[mt][nt][2] + b0;
                Cout[(long)r_hi*N + gj + 1] = c[mt][nt][3] + b1;
            } else {
                int t = gj >> 8;
                int h = (gj >> 5) & 7;
                int d = gj & 31;
                #pragma unroll
                for (int e = 0; e < 4; e++) {
                    int gm = (e < 2) ? r_lo : r_hi;
                    float v = c[mt][nt][e] + ((e & 1) ? b1 : b0);
                    int bb  = gm / POS;
                    int pos = gm % POS;
                    long off = ((long)(bb*NH + h)*POS + pos)*HD + d + (e & 1);
                    if (t == 0)       g_q[off] = v * QSCALE;
                    else if (t == 1)  g_k[off] = v;
                    else              g_v[off] = v;
                }
            }
        }
    }
}

// ---------------------------------------------------------------------------
// Tensor-core neighborhood attention.
// Block = 7x7 query tile of one (b, head, sub-image); dense S[64x176] = Q.K^T
// over the 13x13 halo, masked softmax (+rpb), O[64x32] = P.V. tf32 mma.
// ---------------------------------------------------------------------------
#define HALO  13
#define NKEY  169
#define NKEYP 176
#define QSTR  36
#define KTSTR 184
#define VSTR  40
#define PSTR  180

// dynamic smem word offsets
#define OFF_QS   0
#define OFF_KT   (OFF_QS + 64*QSTR)          // 2304
#define OFF_VS   (OFF_KT + 32*KTSTR)         // 8192
#define OFF_P    (OFF_VS + NKEYP*VSTR)       // 15232
#define OFF_RS   (OFF_P + 64*PSTR)           // 26752
#define OFF_INV  (OFF_RS + NKEY)             // 26921
#define OFF_WOY  (OFF_INV + 49)
#define OFF_WOX  (OFF_WOY + 49)
#define OFF_WBY  (OFF_WOX + 49)
#define OFF_WBX  (OFF_WBY + 49)
#define NATTEN_SMEM_WORDS (OFF_WBX + 49)     // 27166
#define NATTEN_SMEM_BYTES (NATTEN_SMEM_WORDS*4)

__global__ __launch_bounds__(256) void natten_mma_kernel(const float* __restrict__ rpb0,
                                                         const float* __restrict__ rpb1)
{
    extern __shared__ unsigned smem_u[];
    unsigned* Qs = smem_u + OFF_QS;
    unsigned* Kt = smem_u + OFF_KT;
    unsigned* Vs = smem_u + OFF_VS;
    float*    P  = (float*)(smem_u + OFF_P);
    unsigned* Pu = smem_u + OFF_P;
    float*    Rs = (float*)(smem_u + OFF_RS);
    float*    Inv= (float*)(smem_u + OFF_INV);
    int* wOy = (int*)(smem_u + OFF_WOY);
    int* wOx = (int*)(smem_u + OFF_WOX);
    int* wBy = (int*)(smem_u + OFF_WBY);
    int* wBx = (int*)(smem_u + OFF_WBX);

    const int b = blockIdx.z;
    const int h = blockIdx.y;
    const int dil = (h < 4) ? 1 : 2;
    const float* __restrict__ rpb = (h < 4) ? (rpb0 + h*NKEY) : (rpb1 + (h-4)*NKEY);

    int ry, rx, qy0, qx0, L;
    if (dil == 1) {
        L = 56; ry = 0; rx = 0;
        qy0 = (blockIdx.x >> 3) * 7;
        qx0 = (blockIdx.x & 7) * 7;
    } else {
        L = 28;
        int sub = blockIdx.x >> 4;
        ry = sub >> 1; rx = sub & 1;
        int ti = blockIdx.x & 15;
        qy0 = (ti >> 2) * 7;
        qx0 = (ti & 3) * 7;
    }

    int hy0 = qy0 - 3; if (hy0 < 0) hy0 = 0; if (hy0 > L - HALO) hy0 = L - HALO;
    int hx0 = qx0 - 3; if (hx0 < 0) hx0 = 0; if (hx0 > L - HALO) hx0 = L - HALO;

    const long base = ((long)(b*NH + h)) * POS * HD;
    const int tid  = threadIdx.x;
    const int lane = tid & 31;
    const int w    = tid >> 5;
    const int g    = lane >> 2;
    const int tg   = lane & 3;

    // ---- Load Q tile (rows 0..63, zero-pad rows >=49) ----
    for (int item = tid; item < 512; item += 256) {
        int r  = item >> 3;
        int cg = (item & 7) * 4;
        uint4 u = {0,0,0,0};
        if (r < 49) {
            int qy = qy0 + r/7, qx = qx0 + r%7;
            int gy = qy*dil + ry, gx = qx*dil + rx;
            float4 v = *(const float4*)&g_q[base + (long)(gy*WW + gx)*HD + cg];
            u.x=f2tf32(v.x); u.y=f2tf32(v.y); u.z=f2tf32(v.z); u.w=f2tf32(v.w);
        }
        *(uint4*)&Qs[r*QSTR + cg] = u;
    }
    // ---- Load K halo transposed: Kt[d][key], V halo: Vs[key][d] ----
    for (int item = tid; item < NKEY*8; item += 256) {
        int key = item >> 3;
        int dg  = (item & 7) * 4;
        int iy = key / HALO, ix = key % HALO;
        int gy = (hy0 + iy)*dil + ry;
        int gx = (hx0 + ix)*dil + rx;
        long off = base + (long)(gy*WW + gx)*HD + dg;
        float4 kv = *(const float4*)&g_k[off];
        Kt[(dg+0)*KTSTR + key] = f2tf32(kv.x);
        Kt[(dg+1)*KTSTR + key] = f2tf32(kv.y);
        Kt[(dg+2)*KTSTR + key] = f2tf32(kv.z);
        Kt[(dg+3)*KTSTR + key] = f2tf32(kv.w);
        float4 vv = *(const float4*)&g_v[off];
        uint4 u;
        u.x=f2tf32(vv.x); u.y=f2tf32(vv.y); u.z=f2tf32(vv.z); u.w=f2tf32(vv.w);
        *(uint4*)&Vs[key*VSTR + dg] = u;
    }
    // zero pad: Kt cols 169..175, Vs rows 169..175
    for (int item = tid; item < 32*7; item += 256) {
        int d = item / 7, j = item % 7;
        Kt[d*KTSTR + NKEY + j] = 0;
    }
    for (int item = tid; item < 7*8; item += 256) {
        int r = item >> 3, cg = (item & 7)*4;
        uint4 z = {0,0,0,0};
        *(uint4*)&Vs[(NKEY + r)*VSTR + cg] = z;
    }
    if (tid < NKEY) Rs[tid] = rpb[tid];
    if (tid < 49) {
        int qy = qy0 + tid/7, qx = qx0 + tid%7;
        int wsy = qy - 3; if (wsy < 0) wsy = 0; if (wsy > L-7) wsy = L-7;
        int wsx = qx - 3; if (wsx < 0) wsx = 0; if (wsx > L-7) wsx = L-7;
        wOy[tid] = wsy - hy0;  wOx[tid] = wsx - hx0;
        wBy[tid] = wsy - qy + 6; wBx[tid] = wsx - qx + 6;
    }
    __syncthreads();

    // ---- mma1: S = Q.K^T  (88 tiles = 4 m x 22 n, round-robin over 8 warps)
    for (int t = w; t < 88; t += 8) {
        int mt = t / 22;
        int nt = t % 22;
        float acc[4] = {0.f, 0.f, 0.f, 0.f};
        #pragma unroll
        for (int kc = 0; kc < 32; kc += 8) {
            unsigned a0 = Qs[(mt*16 + g    )*QSTR + kc + tg    ];
            unsigned a1 = Qs[(mt*16 + g + 8)*QSTR + kc + tg    ];
            unsigned a2 = Qs[(mt*16 + g    )*QSTR + kc + tg + 4];
            unsigned a3 = Qs[(mt*16 + g + 8)*QSTR + kc + tg + 4];
            unsigned b0 = Kt[(kc + tg    )*KTSTR + nt*8 + g];
            unsigned b1 = Kt[(kc + tg + 4)*KTSTR + nt*8 + g];
            asm volatile(
                "mma.sync.aligned.m16n8k8.row.col.f32.tf32.tf32.f32 "
                "{%0,%1,%2,%3}, {%4,%5,%6,%7}, {%8,%9}, {%0,%1,%2,%3};"
                : "+f"(acc[0]), "+f"(acc[1]), "+f"(acc[2]), "+f"(acc[3])
                : "r"(a0), "r"(a1), "r"(a2), "r"(a3), "r"(b0), "r"(b1));
        }
        #pragma unroll
        for (int e = 0; e < 4; e++) {
            int row = mt*16 + g + ((e >= 2) ? 8 : 0);
            int col = nt*8 + 2*tg + (e & 1);
            float outv;
            if (row >= 49 || col >= NKEY) {
                outv = 0.0f;
            } else {
                int ky = col / HALO, kx = col % HALO;
                int dy = ky - wOy[row], dx = kx - wOx[row];
                if (dy >= 0 && dy < 7 && dx >= 0 && dx < 7)
                    outv = acc[e] + Rs[(wBy[row] + dy)*HALO + wBx[row] + dx];
                else
                    outv = -1e30f;
            }
            P[row*PSTR + col] = outv;
        }
    }
    __syncthreads();

    // ---- softmax per query row (49 rows over 8 warps) ----
    for (int q = w; q < 49; q += 8) {
        float s[6];
        #pragma unroll
        for (int j = 0; j < 6; j++) {
            int cc = lane + 32*j;
            s[j] = (cc < NKEY) ? P[q*PSTR + cc] : -1e30f;
        }
        float m = s[0];
        #pragma unroll
        for (int j = 1; j < 6; j++) m = fmaxf(m, s[j]);
        #pragma unroll
        for (int st = 16; st; st >>= 1)
            m = fmaxf(m, __shfl_xor_sync(0xffffffffu, m, st));
        float sum = 0.0f;
        #pragma unroll
        for (int j = 0; j < 6; j++) {
            s[j] = __expf(s[j] - m);     // -1e30 -> 0
            sum += s[j];
        }
        #pragma unroll
        for (int st = 16; st; st >>= 1)
            sum += __shfl_xor_sync(0xffffffffu, sum, st);
        if (lane == 0) Inv[q] = 1.0f / sum;
        #pragma unroll
        for (int j = 0; j < 6; j++) {
            int cc = lane + 32*j;
            if (cc < NKEY) Pu[q*PSTR + cc] = f2tf32(s[j]);
        }
    }
    __syncthreads();

    // ---- mma2: O = P.V  (warp: mt = w&3, nt pair = (w>>2)*2 + {0,1}) ----
    {
        int mt = w & 3;
        int ntb = (w >> 2) * 2;
        float o[2][4];
        #pragma unroll
        for (int nn = 0; nn < 2; nn++)
            #pragma unroll
            for (int e = 0; e < 4; e++) o[nn][e] = 0.0f;

        for (int kc = 0; kc < NKEYP; kc += 8) {
            unsigned a0 = Pu[(mt*16 + g    )*PSTR + kc + tg    ];
            unsigned a1 = Pu[(mt*16 + g + 8)*PSTR + kc + tg    ];
            unsigned a2 = Pu[(mt*16 + g    )*PSTR + kc + tg + 4];
            unsigned a3 = Pu[(mt*16 + g + 8)*PSTR + kc + tg + 4];
            #pragma unroll
            for (int nn = 0; nn < 2; nn++) {
                unsigned b0 = Vs[(kc + tg    )*VSTR + (ntb+nn)*8 + g];
                unsigned b1 = Vs[(kc + tg + 4)*VSTR + (ntb+nn)*8 + g];
                asm volatile(
                    "mma.sync.aligned.m16n8k8.row.col.f32.tf32.tf32.f32 "
                    "{%0,%1,%2,%3}, {%4,%5,%6,%7}, {%8,%9}, {%0,%1,%2,%3};"
                    : "+f"(o[nn][0]), "+f"(o[nn][1]), "+f"(o[nn][2]), "+f"(o[nn][3])
                    : "r"(a0), "r"(a1), "r"(a2), "r"(a3), "r"(b0), "r"(b1));
            }
        }

        #pragma unroll
        for (int e = 0; e < 4; e++) {
            int row = mt*16 + g + ((e >= 2) ? 8 : 0);
            if (row < 49) {
                float iv = Inv[row];
                int qy = qy0 + row/7, qx = qx0 + row%7;
                int gy = qy*dil + ry, gx = qx*dil + rx;
                long ob = ((long)(b*POS) + gy*WW + gx)*C_ + h*HD;
                #pragma unroll
                for (int nn = 0; nn < 2; nn++) {
                    int col = (ntb+nn)*8 + 2*tg + (e & 1);
                    g_att[ob + col] = o[nn][e] * iv;
                }
            }
        }
    }
}

// ---------------------------------------------------------------------------
extern "C" void kernel_launch(void* const* d_in, const int* in_sizes, int n_in,
                              void* d_out, int out_size)
{
    const float* x      = (const float*)d_in[0];
    const float* w_qkv  = (const float*)d_in[1];
    const float* b_qkv  = (const float*)d_in[2];
    const float* w_proj = (const float*)d_in[3];
    const float* b_proj = (const float*)d_in[4];
    const float* rpb0   = (const float*)d_in[5];
    const float* rpb1   = (const float*)d_in[6];
    float* out = (float*)d_out;

    cudaFuncSetAttribute(natten_mma_kernel,
                         cudaFuncAttributeMaxDynamicSharedMemorySize,
                         NATTEN_SMEM_BYTES);

    dim3 blk(256);
    dim3 grid_qkv((3*C_)/128, TOK/128);   // (6, 49)
    dim3 grid_proj(C_/128,    TOK/128);   // (2, 49)

    gemm_tf32_kernel<<<grid_qkv, blk>>>(x, w_qkv, b_qkv, nullptr, 3*C_, 0);
    natten_mma_kernel<<<dim3(64, NH, B_), 256, NATTEN_SMEM_BYTES>>>(rpb0, rpb1);
    gemm_tf32_kernel<<<grid_proj, blk>>>(nullptr, w_proj, b_proj, out, C_, 1);
}

// round 8
// speedup vs baseline: 1.1463x; 1.1463x over previous
#include <cuda_runtime.h>
#include <math.h>

// Problem constants
#define B_   2
#define HH   56
#define WW   56
#define C_   256
#define NH   8
#define HD   32
#define TOK  (B_*HH*WW)      // 6272
#define POS  (HH*WW)         // 3136
#define QSCALE 0.17677669529663687f   // 32^-0.5

__device__ float g_q[B_*NH*POS*HD];
__device__ float g_k[B_*NH*POS*HD];
__device__ float g_v[B_*NH*POS*HD];
__device__ float g_att[TOK*C_];

__device__ __forceinline__ unsigned f2tf32(float f) {
    unsigned u;
    asm("cvt.rna.tf32.f32 %0, %1;" : "=r"(u) : "f"(f));
    return u;
}

// ---------------------------------------------------------------------------
// tf32 tensor-core GEMM, double-buffered (unchanged from R6 — 26.3us).
// ---------------------------------------------------------------------------
#define ASTR 20
#define BSTR 136
#define NKT  16

__global__ __launch_bounds__(256) void gemm_tf32_kernel(
    const float* __restrict__ A, const float* __restrict__ Bw,
    const float* __restrict__ bias, float* __restrict__ Cout,
    int N, int mode)
{
    __shared__ alignas(16) unsigned As[2][128*ASTR];
    __shared__ alignas(16) unsigned Bs[2][16*BSTR];

    const float* __restrict__ Ap = A ? A : g_att;

    const int tid  = threadIdx.x;
    const int lane = tid & 31;
    const int w    = tid >> 5;
    const int wm   = w >> 1;
    const int wn   = w & 1;
    const int g    = lane >> 2;
    const int tg   = lane & 3;

    const int row0 = blockIdx.y * 128;
    const int col0 = blockIdx.x * 128;

    const int a_r0 = tid >> 2,          a_c0 = (tid & 3) << 2;
    const int a_r1 = (tid + 256) >> 2,  a_c1 = a_c0;
    const int b_r0 = tid >> 5,          b_c0 = (tid & 31) << 2;
    const int b_r1 = (tid + 256) >> 5,  b_c1 = b_c0;

    float c[2][8][4];
    #pragma unroll
    for (int mt = 0; mt < 2; mt++)
        #pragma unroll
        for (int nt = 0; nt < 8; nt++)
            #pragma unroll
            for (int i = 0; i < 4; i++)
                c[mt][nt][i] = 0.0f;

    float4 sa0, sa1, sb0, sb1;

    sa0 = *(const float4*)&Ap[(long)(row0 + a_r0)*256 + a_c0];
    sa1 = *(const float4*)&Ap[(long)(row0 + a_r1)*256 + a_c1];
    sb0 = *(const float4*)&Bw[(long)b_r0*N + col0 + b_c0];
    sb1 = *(const float4*)&Bw[(long)b_r1*N + col0 + b_c1];
    {
        uint4 u;
        u.x=f2tf32(sa0.x); u.y=f2tf32(sa0.y); u.z=f2tf32(sa0.z); u.w=f2tf32(sa0.w);
        *(uint4*)&As[0][a_r0*ASTR + a_c0] = u;
        u.x=f2tf32(sa1.x); u.y=f2tf32(sa1.y); u.z=f2tf32(sa1.z); u.w=f2tf32(sa1.w);
        *(uint4*)&As[0][a_r1*ASTR + a_c1] = u;
        u.x=f2tf32(sb0.x); u.y=f2tf32(sb0.y); u.z=f2tf32(sb0.z); u.w=f2tf32(sb0.w);
        *(uint4*)&Bs[0][b_r0*BSTR + b_c0] = u;
        u.x=f2tf32(sb1.x); u.y=f2tf32(sb1.y); u.z=f2tf32(sb1.z); u.w=f2tf32(sb1.w);
        *(uint4*)&Bs[0][b_r1*BSTR + b_c1] = u;
    }
    __syncthreads();

    #pragma unroll
    for (int kt = 0; kt < NKT; kt++) {
        const int cur = kt & 1;
        const int nxt = cur ^ 1;

        if (kt < NKT-1) {
            int k0 = (kt+1) * 16;
            sa0 = *(const float4*)&Ap[(long)(row0 + a_r0)*256 + k0 + a_c0];
            sa1 = *(const float4*)&Ap[(long)(row0 + a_r1)*256 + k0 + a_c1];
            sb0 = *(const float4*)&Bw[(long)(k0 + b_r0)*N + col0 + b_c0];
            sb1 = *(const float4*)&Bw[(long)(k0 + b_r1)*N + col0 + b_c1];
        }

        #pragma unroll
        for (int kc = 0; kc < 16; kc += 8) {
            unsigned a[2][4], bf[8][2];
            #pragma unroll
            for (int mt = 0; mt < 2; mt++) {
                int rb = wm*32 + mt*16;
                a[mt][0] = As[cur][(rb + g    )*ASTR + kc + tg    ];
                a[mt][1] = As[cur][(rb + g + 8)*ASTR + kc + tg    ];
                a[mt][2] = As[cur][(rb + g    )*ASTR + kc + tg + 4];
                a[mt][3] = As[cur][(rb + g + 8)*ASTR + kc + tg + 4];
            }
            #pragma unroll
            for (int nt = 0; nt < 8; nt++) {
                int cb = wn*64 + nt*8;
                bf[nt][0] = Bs[cur][(kc + tg    )*BSTR + cb + g];
                bf[nt][1] = Bs[cur][(kc + tg + 4)*BSTR + cb + g];
            }
            #pragma unroll
            for (int mt = 0; mt < 2; mt++)
                #pragma unroll
                for (int nt = 0; nt < 8; nt++)
                    asm volatile(
                        "mma.sync.aligned.m16n8k8.row.col.f32.tf32.tf32.f32 "
                        "{%0,%1,%2,%3}, {%4,%5,%6,%7}, {%8,%9}, {%0,%1,%2,%3};"
                        : "+f"(c[mt][nt][0]), "+f"(c[mt][nt][1]),
                          "+f"(c[mt][nt][2]), "+f"(c[mt][nt][3])
                        : "r"(a[mt][0]), "r"(a[mt][1]), "r"(a[mt][2]), "r"(a[mt][3]),
                          "r"(bf[nt][0]), "r"(bf[nt][1]));
        }

        if (kt < NKT-1) {
            uint4 u;
            u.x=f2tf32(sa0.x); u.y=f2tf32(sa0.y); u.z=f2tf32(sa0.z); u.w=f2tf32(sa0.w);
            *(uint4*)&As[nxt][a_r0*ASTR + a_c0] = u;
            u.x=f2tf32(sa1.x); u.y=f2tf32(sa1.y); u.z=f2tf32(sa1.z); u.w=f2tf32(sa1.w);
            *(uint4*)&As[nxt][a_r1*ASTR + a_c1] = u;
            u.x=f2tf32(sb0.x); u.y=f2tf32(sb0.y); u.z=f2tf32(sb0.z); u.w=f2tf32(sb0.w);
            *(uint4*)&Bs[nxt][b_r0*BSTR + b_c0] = u;
            u.x=f2tf32(sb1.x); u.y=f2tf32(sb1.y); u.z=f2tf32(sb1.z); u.w=f2tf32(sb1.w);
            *(uint4*)&Bs[nxt][b_r1*BSTR + b_c1] = u;
        }
        __syncthreads();
    }

    #pragma unroll
    for (int mt = 0; mt < 2; mt++) {
        int r_lo = row0 + wm*32 + mt*16 + g;
        int r_hi = r_lo + 8;
        #pragma unroll
        for (int nt = 0; nt < 8; nt++) {
            int gj = col0 + wn*64 + nt*8 + 2*tg;
            float b0 = bias[gj], b1 = bias[gj+1];
            if (mode == 1) {
                Cout[(long)r_lo*N + gj    ] = c[mt][nt][0] + b0;
                Cout[(long)r_lo*N + gj + 1] = c[mt][nt][1] + b1;
                Cout[(long)r_hi*N + gj    ] = c[mt][nt][2] + b0;
                Cout[(long)r_hi*N + gj + 1] = c[mt][nt][3] + b1;
            } else {
                int t = gj >> 8;
                int h = (gj >> 5) & 7;
                int d = gj & 31;
                #pragma unroll
                for (int e = 0; e < 4; e++) {
                    int gm = (e < 2) ? r_lo : r_hi;
                    float v = c[mt][nt][e] + ((e & 1) ? b1 : b0);
                    int bb  = gm / POS;
                    int pos = gm % POS;
                    long off = ((long)(bb*NH + h)*POS + pos)*HD + d + (e & 1);
                    if (t == 0)       g_q[off] = v * QSCALE;
                    else if (t == 1)  g_k[off] = v;
                    else              g_v[off] = v;
                }
            }
        }
    }
}

// ---------------------------------------------------------------------------
// Scalar tiled neighborhood attention, latency-optimized:
//  - Q tile staged in smem (no per-round global loads)
//  - QK via float4 LDS (K row stride 36 keeps 16B alignment)
//  - AV probabilities via smem broadcast (no 49-shfl chain), 4 accumulators
// ---------------------------------------------------------------------------
#define HALO 13
#define NROW (HALO*HALO)   // 169
#define KS2  36            // K row stride (16B-aligned, mild conflicts only)

__global__ __launch_bounds__(256) void natten_kernel(const float* __restrict__ rpb0,
                                                     const float* __restrict__ rpb1)
{
    __shared__ alignas(16) float Ks[NROW*KS2];   // 24336 B
    __shared__ alignas(16) float Vs[NROW*HD];    // 21632 B
    __shared__ alignas(16) float Qs[49*HD];      //  6272 B
    __shared__ alignas(16) float Ps[8*52];       //  1664 B
    __shared__ alignas(16) float Rs[NROW];       //   676 B

    const int b = blockIdx.z;
    const int h = blockIdx.y;
    const int dil = (h < 4) ? 1 : 2;
    const float* __restrict__ rpb = (h < 4) ? (rpb0 + h*NROW) : (rpb1 + (h-4)*NROW);

    int ry, rx, qy0, qx0, L;
    if (dil == 1) {
        L = 56; ry = 0; rx = 0;
        qy0 = (blockIdx.x >> 3) * 7;
        qx0 = (blockIdx.x & 7) * 7;
    } else {
        L = 28;
        int sub = blockIdx.x >> 4;
        ry = sub >> 1; rx = sub & 1;
        int ti = blockIdx.x & 15;
        qy0 = (ti >> 2) * 7;
        qx0 = (ti & 3) * 7;
    }

    int hy0 = qy0 - 3; if (hy0 < 0) hy0 = 0; if (hy0 > L - HALO) hy0 = L - HALO;
    int hx0 = qx0 - 3; if (hx0 < 0) hx0 = 0; if (hx0 > L - HALO) hx0 = L - HALO;

    const long base = ((long)(b*NH + h)) * POS * HD;
    const int tid = threadIdx.x;

    // Halo K/V load (float4)
    for (int item = tid; item < NROW*8; item += 256) {
        int t  = item >> 3;
        int c  = (item & 7) * 4;
        int iy = t / HALO, ix = t % HALO;
        int gy = (hy0 + iy)*dil + ry;
        int gx = (hx0 + ix)*dil + rx;
        long off = base + (long)(gy*WW + gx)*HD + c;
        *(float4*)&Ks[t*KS2 + c] = *(const float4*)&g_k[off];
        *(float4*)&Vs[t*HD + c]  = *(const float4*)&g_v[off];
    }
    // Q tile load (float4)
    for (int item = tid; item < 49*8; item += 256) {
        int q = item >> 3;
        int c = (item & 7) * 4;
        int gy = (qy0 + q/7)*dil + ry;
        int gx = (qx0 + q%7)*dil + rx;
        *(float4*)&Qs[q*HD + c] =
            *(const float4*)&g_q[base + (long)(gy*WW + gx)*HD + c];
    }
    for (int t = tid; t < NROW; t += 256) Rs[t] = rpb[t];
    __syncthreads();

    const int w    = tid >> 5;          // 0..7
    const int lane = tid & 31;

    const int n1 = lane;
    const int i1 = n1 / 7, j1 = n1 % 7;
    const bool has2 = (lane < 17);
    const int n2 = 32 + lane;
    const int i2 = has2 ? n2 / 7 : 0;
    const int j2 = has2 ? n2 % 7 : 0;
    const int c1 = i1*HALO + j1;        // neighbor offsets within halo
    const int c2 = i2*HALO + j2;

    #pragma unroll
    for (int t = 0; t < 7; t++) {
        int q = w + 8*t;
        if (q >= 49) break;
        int qy = qy0 + q / 7;
        int qx = qx0 + q % 7;

        int wsy = qy - 3; if (wsy < 0) wsy = 0; if (wsy > L-7) wsy = L-7;
        int wsx = qx - 3; if (wsx < 0) wsx = 0; if (wsx > L-7) wsx = L-7;
        int oy = wsy - hy0, ox = wsx - hx0;
        int robase = oy*HALO + ox;
        int biy = wsy - qy + 6, bix = wsx - qx + 6;

        // QK: float4 smem dots, 2 neighbors per lane
        const float* k1 = &Ks[(robase + c1) * KS2];
        const float* k2 = &Ks[(robase + c2) * KS2];
        const float* qp = &Qs[q*HD];

        float a1 = 0.0f, a2 = 0.0f;
        #pragma unroll
        for (int dg = 0; dg < 8; dg++) {
            float4 qv  = *(const float4*)&qp[dg*4];
            float4 k1v = *(const float4*)&k1[dg*4];
            float4 k2v = *(const float4*)&k2[dg*4];
            a1 += qv.x*k1v.x + qv.y*k1v.y + qv.z*k1v.z + qv.w*k1v.w;
            a2 += qv.x*k2v.x + qv.y*k2v.y + qv.z*k2v.z + qv.w*k2v.w;
        }

        float l0 = a1 + Rs[(biy + i1)*HALO + bix + j1];
        float l1 = has2 ? (a2 + Rs[(biy + i2)*HALO + bix + j2]) : -1e30f;

        float mx = fmaxf(l0, l1);
        #pragma unroll
        for (int s = 16; s; s >>= 1)
            mx = fmaxf(mx, __shfl_xor_sync(0xffffffffu, mx, s));

        float p0 = __expf(l0 - mx);
        float p1 = has2 ? __expf(l1 - mx) : 0.0f;

        float sum = p0 + p1;
        #pragma unroll
        for (int s = 16; s; s >>= 1)
            sum += __shfl_xor_sync(0xffffffffu, sum, s);
        float inv = 1.0f / sum;

        // Publish probabilities to smem for broadcast AV
        Ps[w*52 + lane] = p0;
        if (has2) Ps[w*52 + 32 + lane] = p1;
        __syncwarp();

        // AV: 4 independent accumulators, float4 p broadcast, lane = dim
        float ac0 = 0.f, ac1 = 0.f, ac2 = 0.f, ac3 = 0.f;
        #pragma unroll
        for (int nb = 0; nb < 12; nb++) {
            float4 pp = *(const float4*)&Ps[w*52 + nb*4];
            int n0 = nb*4;
            ac0 += pp.x * Vs[(robase + (n0  )/7*HALO + (n0  )%7)*HD + lane];
            ac1 += pp.y * Vs[(robase + (n0+1)/7*HALO + (n0+1)%7)*HD + lane];
            ac2 += pp.z * Vs[(robase + (n0+2)/7*HALO + (n0+2)%7)*HD + lane];
            ac3 += pp.w * Vs[(robase + (n0+3)/7*HALO + (n0+3)%7)*HD + lane];
        }
        // neighbor 48
        ac0 += Ps[w*52 + 48] * Vs[(robase + 6*HALO + 6)*HD + lane];

        int gy = qy*dil + ry;
        int gx = qx*dil + rx;
        g_att[((long)(b*POS) + gy*WW + gx)*C_ + h*HD + lane] =
            (ac0 + ac1 + ac2 + ac3) * inv;
    }
}

// ---------------------------------------------------------------------------
extern "C" void kernel_launch(void* const* d_in, const int* in_sizes, int n_in,
                              void* d_out, int out_size)
{
    const float* x      = (const float*)d_in[0];
    const float* w_qkv  = (const float*)d_in[1];
    const float* b_qkv  = (const float*)d_in[2];
    const float* w_proj = (const float*)d_in[3];
    const float* b_proj = (const float*)d_in[4];
    const float* rpb0   = (const float*)d_in[5];
    const float* rpb1   = (const float*)d_in[6];
    float* out = (float*)d_out;

    dim3 blk(256);
    dim3 grid_qkv((3*C_)/128, TOK/128);   // (6, 49)
    dim3 grid_proj(C_/128,    TOK/128);   // (2, 49)

    gemm_tf32_kernel<<<grid_qkv, blk>>>(x, w_qkv, b_qkv, nullptr, 3*C_, 0);
    natten_kernel<<<dim3(64, NH, B_), 256>>>(rpb0, rpb1);
    gemm_tf32_kernel<<<grid_proj, blk>>>(nullptr, w_proj, b_proj, out, C_, 1);
}